// round 9
// baseline (speedup 1.0000x reference)
#include <cuda_runtime.h>
#include <cuda_fp16.h>
#include <cstdint>

#define NB   4
#define NSEQ 4096
#define CDIM 512
#define DDIM 64

// fp16 scratch (allocation-free rule: __device__ globals)
__device__ __half g_qh[NB * NSEQ * DDIM];   // Q = (x @ g) * log2e
__device__ __half g_kh[NB * NSEQ * DDIM];   // K = input_h @ f
__device__ __half g_hh[NB * NSEQ * CDIM];   // input_h fp16

#define SWZ(x) ((x) ^ (((x) >> 3) & 0x70))
#define ONES_H2 0x3C003C00u

// ---------------------------------------------------------------------------
__device__ __forceinline__ uint32_t smem_u32(const void* p) {
    uint32_t a;
    asm("{ .reg .u64 t; cvta.to.shared.u64 t, %1; cvt.u32.u64 %0, t; }" : "=r"(a) : "l"(p));
    return a;
}
__device__ __forceinline__ void cp16(uint32_t s, const void* g) {
    asm volatile("cp.async.cg.shared.global [%0], [%1], 16;" :: "r"(s), "l"(g));
}
#define CP_COMMIT() asm volatile("cp.async.commit_group;" ::: "memory")
#define CP_WAIT0()  asm volatile("cp.async.wait_group 0;" ::: "memory")
#define CP_WAIT1()  asm volatile("cp.async.wait_group 1;" ::: "memory")

__device__ __forceinline__ void ldsm4(uint32_t* r, uint32_t a) {
    asm volatile("ldmatrix.sync.aligned.m8n8.x4.shared.b16 {%0,%1,%2,%3}, [%4];"
        : "=r"(r[0]), "=r"(r[1]), "=r"(r[2]), "=r"(r[3]) : "r"(a));
}
__device__ __forceinline__ void ldsm4t(uint32_t* r, uint32_t a) {
    asm volatile("ldmatrix.sync.aligned.m8n8.x4.trans.shared.b16 {%0,%1,%2,%3}, [%4];"
        : "=r"(r[0]), "=r"(r[1]), "=r"(r[2]), "=r"(r[3]) : "r"(a));
}
// fp32-accum HMMA
__device__ __forceinline__ void mma16816(float* d, const uint32_t* a,
                                         uint32_t b0, uint32_t b1) {
    asm volatile(
        "mma.sync.aligned.m16n8k16.row.col.f32.f16.f16.f32 "
        "{%0,%1,%2,%3}, {%4,%5,%6,%7}, {%8,%9}, {%0,%1,%2,%3};"
        : "+f"(d[0]), "+f"(d[1]), "+f"(d[2]), "+f"(d[3])
        : "r"(a[0]), "r"(a[1]), "r"(a[2]), "r"(a[3]), "r"(b0), "r"(b1));
}
// fp16-accum HMMA
__device__ __forceinline__ void mma16816f16(uint32_t* d, const uint32_t* a,
                                            uint32_t b0, uint32_t b1) {
    asm volatile(
        "mma.sync.aligned.m16n8k16.row.col.f16.f16.f16.f16 "
        "{%0,%1}, {%2,%3,%4,%5}, {%6,%7}, {%0,%1};"
        : "+r"(d[0]), "+r"(d[1])
        : "r"(a[0]), "r"(a[1]), "r"(a[2]), "r"(a[3]), "r"(b0), "r"(b1));
}
__device__ __forceinline__ uint32_t ex2h2(uint32_t v) {
    uint32_t r; asm("ex2.approx.f16x2 %0, %1;" : "=r"(r) : "r"(v)); return r;
}
__device__ __forceinline__ void sts128(uint32_t a, uint32_t v0, uint32_t v1,
                                       uint32_t v2, uint32_t v3) {
    asm volatile("st.shared.v4.b32 [%0], {%1,%2,%3,%4};"
        :: "r"(a), "r"(v0), "r"(v1), "r"(v2), "r"(v3) : "memory");
}

// ---------------------------------------------------------------------------
// Projection via HMMA: O[16384,64] = fp16(A[16384,512]) @ fp16(W[512,64]).
// Q output pre-scaled by log2e. doF writes g_hh too.
// ---------------------------------------------------------------------------
__global__ __launch_bounds__(256) void proj_kernel(
    const float* __restrict__ x, const float* __restrict__ in_h,
    const float* __restrict__ f, const float* __restrict__ g)
{
    const bool doF = (blockIdx.z == 1);
    const float* A  = doF ? in_h : x;
    const float* Wm = doF ? f : g;
    __half* O       = doF ? g_kh : g_qh;
    const float scaleO = doF ? 1.0f : 1.4426950408889634f;

    __shared__ char psm[16384 + 8192];
    const uint32_t sa = smem_u32(psm);
    const uint32_t sw = sa + 16384;

    const int m0  = blockIdx.x * 128;
    const int tid = threadIdx.x;
    const int wid = tid >> 5, lane = tid & 31;
    const int l16 = lane & 15, lhi = lane & 16;
    const int w16 = wid * 16;

    float acc[8][4];
    #pragma unroll
    for (int i = 0; i < 8; i++)
        #pragma unroll
        for (int j = 0; j < 4; j++) acc[i][j] = 0.f;

    for (int k0 = 0; k0 < CDIM; k0 += 64) {
        #pragma unroll
        for (int i = 0; i < 4; i++) {
            int lin = tid + i * 256;
            int row = lin >> 3, c8 = lin & 7;
            const float4* ap = (const float4*)(A + (size_t)(m0 + row) * CDIM + k0 + c8 * 8);
            float4 v0 = ap[0], v1 = ap[1];
            __half2 h0 = __floats2half2_rn(v0.x, v0.y);
            __half2 h1 = __floats2half2_rn(v0.z, v0.w);
            __half2 h2 = __floats2half2_rn(v1.x, v1.y);
            __half2 h3 = __floats2half2_rn(v1.z, v1.w);
            sts128(sa + SWZ(row * 128 + c8 * 16),
                   *(uint32_t*)&h0, *(uint32_t*)&h1, *(uint32_t*)&h2, *(uint32_t*)&h3);
            if (doF) {
                uint4 pk = make_uint4(*(uint32_t*)&h0, *(uint32_t*)&h1,
                                      *(uint32_t*)&h2, *(uint32_t*)&h3);
                *(uint4*)(g_hh + (size_t)(m0 + row) * CDIM + k0 + c8 * 8) = pk;
            }
        }
        #pragma unroll
        for (int i = 0; i < 2; i++) {
            int lin = tid + i * 256;
            int kk = lin >> 3, n8 = lin & 7;
            const float4* wp = (const float4*)(Wm + (size_t)(k0 + kk) * DDIM + n8 * 8);
            float4 v0 = wp[0], v1 = wp[1];
            __half2 h0 = __floats2half2_rn(v0.x, v0.y);
            __half2 h1 = __floats2half2_rn(v0.z, v0.w);
            __half2 h2 = __floats2half2_rn(v1.x, v1.y);
            __half2 h3 = __floats2half2_rn(v1.z, v1.w);
            sts128(sw + SWZ(kk * 128 + n8 * 16),
                   *(uint32_t*)&h0, *(uint32_t*)&h1, *(uint32_t*)&h2, *(uint32_t*)&h3);
        }
        __syncthreads();

        #pragma unroll
        for (int ks = 0; ks < 4; ks++) {
            uint32_t a[4];
            ldsm4(a, sa + SWZ((w16 + l16) * 128 + ks * 32 + lhi));
            #pragma unroll
            for (int cb = 0; cb < 4; cb++) {
                uint32_t b[4];
                ldsm4t(b, sw + SWZ((ks * 16 + l16) * 128 + cb * 32 + lhi));
                mma16816(acc[2 * cb],     a, b[0], b[1]);
                mma16816(acc[2 * cb + 1], a, b[2], b[3]);
            }
        }
        __syncthreads();
    }

    const int r = w16 + (lane >> 2);
    const int cb2 = (lane & 3) * 2;
    #pragma unroll
    for (int nt = 0; nt < 8; nt++) {
        __half2 v0 = __floats2half2_rn(scaleO * acc[nt][0], scaleO * acc[nt][1]);
        __half2 v1 = __floats2half2_rn(scaleO * acc[nt][2], scaleO * acc[nt][3]);
        *(__half2*)(O + (size_t)(m0 + r) * DDIM + nt * 8 + cb2)     = v0;
        *(__half2*)(O + (size_t)(m0 + r + 8) * DDIM + nt * 8 + cb2) = v1;
    }
}

// ---------------------------------------------------------------------------
// Fused attention: 256 thr / 8 warps = (4 qw) x (2 cw); warp tile 32q x 64c;
// CTA tile 128q x 128c; KT=64; 3-stage cp.async ring, ONE barrier per iter;
// 2 CTAs/SM. Register-P, fp16 S-accum, ex2, ones-MMA denom (cw0 only).
// SMEM: Q 16K | K 3x8K | H 3x16K | dinv 0.5K = 90624 B
// ---------------------------------------------------------------------------
#define SM_Q     0
#define SM_K     16384
#define SM_H     40960
#define SM_DINV  90112
#define SMEM_TOTAL 90624

__global__ __launch_bounds__(256, 2)
void attn_kernel(const float* __restrict__ x, const float* __restrict__ gamma,
                 float* __restrict__ out)
{
    extern __shared__ char smem[];
    const uint32_t sb = smem_u32(smem);
    const int tid = threadIdx.x;
    const int wid = tid >> 5, lane = tid & 31;
    const int l16 = lane & 15;
    const int lhi = lane & 16;
    const int qw  = wid >> 1;            // 0..3
    const int cw  = wid & 1;             // 0..1
    const int q0  = qw * 32;

    const int qt = blockIdx.x, ch = blockIdx.y, b = blockIdx.z;
    const int qbase = qt * 128, chbase = ch * 128;
    const size_t boff = (size_t)b * NSEQ;

    float acc[2][8][4];                  // [q-subtile][c-block][frag]
    #pragma unroll
    for (int i = 0; i < 2; i++)
        #pragma unroll
        for (int j = 0; j < 8; j++)
            #pragma unroll
            for (int k = 0; k < 4; k++) acc[i][j][k] = 0.f;
    float dacc[2][4] = {{0.f,0.f,0.f,0.f},{0.f,0.f,0.f,0.f}};

    // staging coords
    const int srow = tid >> 3, sc8 = tid & 7;   // Q/K: 32 rows per step
    const int hk = tid >> 4, hc = tid & 15;     // H: 16 rows per step
    const int hpanel = hc >> 3, hpc8 = hc & 7;

    // ---- Prologue ----
    #pragma unroll
    for (int i = 0; i < 4; i++) {
        int row = srow + i * 32;
        cp16(sb + SM_Q + SWZ(row * 128 + sc8 * 16),
             g_qh + (boff + qbase + row) * DDIM + sc8 * 8);
    }
    #pragma unroll
    for (int i = 0; i < 2; i++) {
        int row = srow + i * 32;
        cp16(sb + SM_K + SWZ(row * 128 + sc8 * 16),
             g_kh + (boff + row) * DDIM + sc8 * 8);
    }
    #pragma unroll
    for (int i = 0; i < 4; i++) {
        int k = hk + i * 16;
        cp16(sb + SM_H + hpanel * 8192 + SWZ(k * 128 + hpc8 * 16),
             g_hh + (boff + k) * CDIM + chbase + hc * 8);
    }
    CP_COMMIT();
    #pragma unroll
    for (int i = 0; i < 2; i++) {
        int row = srow + i * 32;
        cp16(sb + SM_K + 8192 + SWZ(row * 128 + sc8 * 16),
             g_kh + (boff + 64 + row) * DDIM + sc8 * 8);
    }
    #pragma unroll
    for (int i = 0; i < 4; i++) {
        int k = hk + i * 16;
        cp16(sb + SM_H + 16384 + hpanel * 8192 + SWZ(k * 128 + hpc8 * 16),
             g_hh + (boff + 64 + k) * CDIM + chbase + hc * 8);
    }
    CP_COMMIT();

    for (int t = 0; t < 64; t++) {
        if (t < 63) { CP_WAIT1(); } else { CP_WAIT0(); }
        __syncthreads();   // publish tile t; WAR: stage (t+2)%3 free

        if (t < 62) {
            const int kt2 = (t + 2) * 64;
            const int s2 = (t + 2) % 3;
            const uint32_t kbuf = sb + SM_K + s2 * 8192;
            const uint32_t hbuf = sb + SM_H + s2 * 16384;
            #pragma unroll
            for (int i = 0; i < 2; i++) {
                int row = srow + i * 32;
                cp16(kbuf + SWZ(row * 128 + sc8 * 16),
                     g_kh + (boff + kt2 + row) * DDIM + sc8 * 8);
            }
            #pragma unroll
            for (int i = 0; i < 4; i++) {
                int k = hk + i * 16;
                cp16(hbuf + hpanel * 8192 + SWZ(k * 128 + hpc8 * 16),
                     g_hh + (boff + kt2 + k) * CDIM + chbase + hc * 8);
            }
            CP_COMMIT();
        }

        const int st = t % 3;
        const uint32_t kb = sb + SM_K + st * 8192;
        const uint32_t hb = sb + SM_H + st * 16384 + cw * 8192;

        // ---- S = Q @ K^T : 32q x 64k, fp16 accum ----
        // sacc[h][qt][0..7]; [0..3] = k-cols 0..15 of half h, [4..7] = 16..31
        uint32_t sacc[2][2][8];
        #pragma unroll
        for (int h = 0; h < 2; h++)
            #pragma unroll
            for (int u = 0; u < 2; u++)
                #pragma unroll
                for (int j = 0; j < 8; j++) sacc[h][u][j] = 0u;

        #pragma unroll
        for (int ks = 0; ks < 4; ks++) {
            uint32_t qa0[4], qa1[4];
            ldsm4(qa0, sb + SM_Q + SWZ((q0 + l16) * 128 + ks * 32 + lhi));
            ldsm4(qa1, sb + SM_Q + SWZ((q0 + 16 + l16) * 128 + ks * 32 + lhi));
            #pragma unroll
            for (int h = 0; h < 2; h++) {
                uint32_t b0[4], b1[4];
                ldsm4(b0, kb + SWZ((h * 32 + l16) * 128 + ks * 32 + lhi));
                ldsm4(b1, kb + SWZ((h * 32 + 16 + l16) * 128 + ks * 32 + lhi));
                mma16816f16(&sacc[h][0][0], qa0, b0[0], b0[2]);
                mma16816f16(&sacc[h][0][2], qa0, b0[1], b0[3]);
                mma16816f16(&sacc[h][0][4], qa0, b1[0], b1[2]);
                mma16816f16(&sacc[h][0][6], qa0, b1[1], b1[3]);
                mma16816f16(&sacc[h][1][0], qa1, b0[0], b0[2]);
                mma16816f16(&sacc[h][1][2], qa1, b0[1], b0[3]);
                mma16816f16(&sacc[h][1][4], qa1, b1[0], b1[2]);
                mma16816f16(&sacc[h][1][6], qa1, b1[1], b1[3]);
            }
        }

        // ---- P = 2^S in place ----
        #pragma unroll
        for (int h = 0; h < 2; h++)
            #pragma unroll
            for (int u = 0; u < 2; u++)
                #pragma unroll
                for (int j = 0; j < 8; j++) sacc[h][u][j] = ex2h2(sacc[h][u][j]);

        // ---- denominators (cw0 only): dacc[qt] += P @ ones ----
        if (cw == 0) {
            #pragma unroll
            for (int u = 0; u < 2; u++) {
                mma16816(dacc[u], &sacc[0][u][0], ONES_H2, ONES_H2);
                mma16816(dacc[u], &sacc[0][u][4], ONES_H2, ONES_H2);
                mma16816(dacc[u], &sacc[1][u][0], ONES_H2, ONES_H2);
                mma16816(dacc[u], &sacc[1][u][4], ONES_H2, ONES_H2);
            }
        }

        // ---- PV: O += P @ H (32q x 64c) ----
        #pragma unroll
        for (int h = 0; h < 2; h++) {
            #pragma unroll
            for (int kpl = 0; kpl < 2; kpl++) {
                const int kk = h * 32 + kpl * 16;
                const uint32_t* a0 = &sacc[h][0][kpl * 4];
                const uint32_t* a1 = &sacc[h][1][kpl * 4];
                #pragma unroll
                for (int cb = 0; cb < 4; cb++) {
                    uint32_t r[4];
                    ldsm4t(r, hb + SWZ((kk + l16) * 128 + cb * 32 + lhi));
                    mma16816(acc[0][2 * cb],     a0, r[0], r[1]);
                    mma16816(acc[0][2 * cb + 1], a0, r[2], r[3]);
                    mma16816(acc[1][2 * cb],     a1, r[0], r[1]);
                    mma16816(acc[1][2 * cb + 1], a1, r[2], r[3]);
                }
            }
        }
    }

    // ---- broadcast denominators (cw0 -> all) ----
    float* dinv = (float*)(smem + SM_DINV);
    if (cw == 0 && (lane & 3) == 0) {
        dinv[q0 + (lane >> 2)]      = 1.0f / dacc[0][0];
        dinv[q0 + 8 + (lane >> 2)]  = 1.0f / dacc[0][2];
        dinv[q0 + 16 + (lane >> 2)] = 1.0f / dacc[1][0];
        dinv[q0 + 24 + (lane >> 2)] = 1.0f / dacc[1][2];
    }
    __syncthreads();

    // ---- epilogue: out = gamma * o / denom + x ----
    const float gv = gamma[0];
    #pragma unroll
    for (int u = 0; u < 2; u++) {
        const int r0 = q0 + u * 16 + (lane >> 2);
        const float s0 = gv * dinv[r0];
        const float s1 = gv * dinv[r0 + 8];
        #pragma unroll
        for (int j = 0; j < 8; j++) {
            const int c = chbase + cw * 64 + j * 8 + (lane & 3) * 2;
            size_t g0 = (boff + qbase + r0) * CDIM + c;
            size_t g1 = g0 + (size_t)8 * CDIM;
            float2 xv0 = *(const float2*)(x + g0);
            float2 xv1 = *(const float2*)(x + g1);
            float2 o0, o1;
            o0.x = s0 * acc[u][j][0] + xv0.x;
            o0.y = s0 * acc[u][j][1] + xv0.y;
            o1.x = s1 * acc[u][j][2] + xv1.x;
            o1.y = s1 * acc[u][j][3] + xv1.y;
            *(float2*)(out + g0) = o0;
            *(float2*)(out + g1) = o1;
        }
    }
}

// ---------------------------------------------------------------------------
extern "C" void kernel_launch(void* const* d_in, const int* in_sizes, int n_in,
                              void* d_out, int out_size)
{
    const float* x     = (const float*)d_in[0];
    const float* in_h  = (const float*)d_in[1];
    const float* f     = (const float*)d_in[2];
    const float* g     = (const float*)d_in[3];
    const float* gamma = (const float*)d_in[4];
    float* out = (float*)d_out;

    cudaFuncSetAttribute(attn_kernel, cudaFuncAttributeMaxDynamicSharedMemorySize, SMEM_TOTAL);

    proj_kernel<<<dim3((NB * NSEQ) / 128, 1, 2), 256>>>(x, in_h, f, g);
    attn_kernel<<<dim3(NSEQ / 128, 4, NB), 256, SMEM_TOTAL>>>(x, gamma, out);
}

// round 10
// speedup vs baseline: 1.4774x; 1.4774x over previous
#include <cuda_runtime.h>
#include <cuda_fp16.h>
#include <cstdint>

#define NB   4
#define NSEQ 4096
#define CDIM 512
#define DDIM 64

// fp16 scratch (allocation-free rule: __device__ globals)
__device__ __half g_qh[NB * NSEQ * DDIM];   // Q = (x @ g) * log2e
__device__ __half g_kh[NB * NSEQ * DDIM];   // K = input_h @ f
__device__ __half g_hh[NB * NSEQ * CDIM];   // input_h fp16

#define SWZ(x) ((x) ^ (((x) >> 3) & 0x70))
#define ONES_H2 0x3C003C00u

// ---------------------------------------------------------------------------
__device__ __forceinline__ uint32_t smem_u32(const void* p) {
    uint32_t a;
    asm("{ .reg .u64 t; cvta.to.shared.u64 t, %1; cvt.u32.u64 %0, t; }" : "=r"(a) : "l"(p));
    return a;
}
__device__ __forceinline__ void cp16(uint32_t s, const void* g) {
    asm volatile("cp.async.cg.shared.global [%0], [%1], 16;" :: "r"(s), "l"(g));
}
#define CP_COMMIT() asm volatile("cp.async.commit_group;" ::: "memory")
#define CP_WAIT0()  asm volatile("cp.async.wait_group 0;" ::: "memory")
#define CP_WAIT1()  asm volatile("cp.async.wait_group 1;" ::: "memory")

__device__ __forceinline__ void ldsm4(uint32_t* r, uint32_t a) {
    asm volatile("ldmatrix.sync.aligned.m8n8.x4.shared.b16 {%0,%1,%2,%3}, [%4];"
        : "=r"(r[0]), "=r"(r[1]), "=r"(r[2]), "=r"(r[3]) : "r"(a));
}
__device__ __forceinline__ void ldsm4t(uint32_t* r, uint32_t a) {
    asm volatile("ldmatrix.sync.aligned.m8n8.x4.trans.shared.b16 {%0,%1,%2,%3}, [%4];"
        : "=r"(r[0]), "=r"(r[1]), "=r"(r[2]), "=r"(r[3]) : "r"(a));
}
// fp32-accum HMMA
__device__ __forceinline__ void mma16816(float* d, const uint32_t* a,
                                         uint32_t b0, uint32_t b1) {
    asm volatile(
        "mma.sync.aligned.m16n8k16.row.col.f32.f16.f16.f32 "
        "{%0,%1,%2,%3}, {%4,%5,%6,%7}, {%8,%9}, {%0,%1,%2,%3};"
        : "+f"(d[0]), "+f"(d[1]), "+f"(d[2]), "+f"(d[3])
        : "r"(a[0]), "r"(a[1]), "r"(a[2]), "r"(a[3]), "r"(b0), "r"(b1));
}
// fp16-accum HMMA
__device__ __forceinline__ void mma16816f16(uint32_t* d, const uint32_t* a,
                                            uint32_t b0, uint32_t b1) {
    asm volatile(
        "mma.sync.aligned.m16n8k16.row.col.f16.f16.f16.f16 "
        "{%0,%1}, {%2,%3,%4,%5}, {%6,%7}, {%0,%1};"
        : "+r"(d[0]), "+r"(d[1])
        : "r"(a[0]), "r"(a[1]), "r"(a[2]), "r"(a[3]), "r"(b0), "r"(b1));
}
__device__ __forceinline__ uint32_t ex2h2(uint32_t v) {
    uint32_t r; asm("ex2.approx.f16x2 %0, %1;" : "=r"(r) : "r"(v)); return r;
}
__device__ __forceinline__ void sts128(uint32_t a, uint32_t v0, uint32_t v1,
                                       uint32_t v2, uint32_t v3) {
    asm volatile("st.shared.v4.b32 [%0], {%1,%2,%3,%4};"
        :: "r"(a), "r"(v0), "r"(v1), "r"(v2), "r"(v3) : "memory");
}

// ---------------------------------------------------------------------------
// Projection via HMMA: O[16384,64] = fp16(A[16384,512]) @ fp16(W[512,64]).
// Q output pre-scaled by log2e. doF writes g_hh too.
// ---------------------------------------------------------------------------
__global__ __launch_bounds__(256) void proj_kernel(
    const float* __restrict__ x, const float* __restrict__ in_h,
    const float* __restrict__ f, const float* __restrict__ g)
{
    const bool doF = (blockIdx.z == 1);
    const float* A  = doF ? in_h : x;
    const float* Wm = doF ? f : g;
    __half* O       = doF ? g_kh : g_qh;
    const float scaleO = doF ? 1.0f : 1.4426950408889634f;

    __shared__ char psm[16384 + 8192];
    const uint32_t sa = smem_u32(psm);
    const uint32_t sw = sa + 16384;

    const int m0  = blockIdx.x * 128;
    const int tid = threadIdx.x;
    const int wid = tid >> 5, lane = tid & 31;
    const int l16 = lane & 15, lhi = lane & 16;
    const int w16 = wid * 16;

    float acc[8][4];
    #pragma unroll
    for (int i = 0; i < 8; i++)
        #pragma unroll
        for (int j = 0; j < 4; j++) acc[i][j] = 0.f;

    for (int k0 = 0; k0 < CDIM; k0 += 64) {
        #pragma unroll
        for (int i = 0; i < 4; i++) {
            int lin = tid + i * 256;
            int row = lin >> 3, c8 = lin & 7;
            const float4* ap = (const float4*)(A + (size_t)(m0 + row) * CDIM + k0 + c8 * 8);
            float4 v0 = ap[0], v1 = ap[1];
            __half2 h0 = __floats2half2_rn(v0.x, v0.y);
            __half2 h1 = __floats2half2_rn(v0.z, v0.w);
            __half2 h2 = __floats2half2_rn(v1.x, v1.y);
            __half2 h3 = __floats2half2_rn(v1.z, v1.w);
            sts128(sa + SWZ(row * 128 + c8 * 16),
                   *(uint32_t*)&h0, *(uint32_t*)&h1, *(uint32_t*)&h2, *(uint32_t*)&h3);
            if (doF) {
                uint4 pk = make_uint4(*(uint32_t*)&h0, *(uint32_t*)&h1,
                                      *(uint32_t*)&h2, *(uint32_t*)&h3);
                *(uint4*)(g_hh + (size_t)(m0 + row) * CDIM + k0 + c8 * 8) = pk;
            }
        }
        #pragma unroll
        for (int i = 0; i < 2; i++) {
            int lin = tid + i * 256;
            int kk = lin >> 3, n8 = lin & 7;
            const float4* wp = (const float4*)(Wm + (size_t)(k0 + kk) * DDIM + n8 * 8);
            float4 v0 = wp[0], v1 = wp[1];
            __half2 h0 = __floats2half2_rn(v0.x, v0.y);
            __half2 h1 = __floats2half2_rn(v0.z, v0.w);
            __half2 h2 = __floats2half2_rn(v1.x, v1.y);
            __half2 h3 = __floats2half2_rn(v1.z, v1.w);
            sts128(sw + SWZ(kk * 128 + n8 * 16),
                   *(uint32_t*)&h0, *(uint32_t*)&h1, *(uint32_t*)&h2, *(uint32_t*)&h3);
        }
        __syncthreads();

        #pragma unroll
        for (int ks = 0; ks < 4; ks++) {
            uint32_t a[4];
            ldsm4(a, sa + SWZ((w16 + l16) * 128 + ks * 32 + lhi));
            #pragma unroll
            for (int cb = 0; cb < 4; cb++) {
                uint32_t b[4];
                ldsm4t(b, sw + SWZ((ks * 16 + l16) * 128 + cb * 32 + lhi));
                mma16816(acc[2 * cb],     a, b[0], b[1]);
                mma16816(acc[2 * cb + 1], a, b[2], b[3]);
            }
        }
        __syncthreads();
    }

    const int r = w16 + (lane >> 2);
    const int cb2 = (lane & 3) * 2;
    #pragma unroll
    for (int nt = 0; nt < 8; nt++) {
        __half2 v0 = __floats2half2_rn(scaleO * acc[nt][0], scaleO * acc[nt][1]);
        __half2 v1 = __floats2half2_rn(scaleO * acc[nt][2], scaleO * acc[nt][3]);
        *(__half2*)(O + (size_t)(m0 + r) * DDIM + nt * 8 + cb2)     = v0;
        *(__half2*)(O + (size_t)(m0 + r + 8) * DDIM + nt * 8 + cb2) = v1;
    }
}

// ---------------------------------------------------------------------------
// Fused attention (R8 structure + fp16 PV accumulation).
// 256 thr / 8 warps; warp tile 16q x 128c; CTA 128q x 128c; KT=64; 3-stage
// cp.async ring, ONE barrier per iter; 2 CTAs/SM; per-warp ones-MMA denom.
// SMEM: Q 16K | K 3x8K | H 3x16K = 90112 B
// ---------------------------------------------------------------------------
#define SM_Q     0
#define SM_K     16384
#define SM_H     40960
#define SMEM_TOTAL 90112

__global__ __launch_bounds__(256, 2)
void attn_kernel(const float* __restrict__ x, const float* __restrict__ gamma,
                 float* __restrict__ out)
{
    extern __shared__ char smem[];
    const uint32_t sb = smem_u32(smem);
    const int tid = threadIdx.x;
    const int wid = tid >> 5, lane = tid & 31;
    const int l16 = lane & 15;
    const int lhi = lane & 16;
    const int q0  = wid * 16;

    const int qt = blockIdx.x, ch = blockIdx.y, b = blockIdx.z;
    const int qbase = qt * 128, chbase = ch * 128;
    const size_t boff = (size_t)b * NSEQ;

    // fp16 accumulators: 16 n8-blocks x {rows r, rows r+8} packed f16x2
    uint32_t acc16[16][2];
    #pragma unroll
    for (int j = 0; j < 16; j++) { acc16[j][0] = 0u; acc16[j][1] = 0u; }
    float dacc[4] = {0.f, 0.f, 0.f, 0.f};
    uint32_t qf[4][4];

    // staging coords
    const int srow = tid >> 3, sc8 = tid & 7;   // Q/K: 32 rows per step
    const int hk = tid >> 4, hc = tid & 15;     // H: 16 rows per step
    const int hpanel = hc >> 3, hpc8 = hc & 7;

    // ---- Prologue ----
    #pragma unroll
    for (int i = 0; i < 4; i++) {
        int row = srow + i * 32;
        cp16(sb + SM_Q + SWZ(row * 128 + sc8 * 16),
             g_qh + (boff + qbase + row) * DDIM + sc8 * 8);
    }
    #pragma unroll
    for (int i = 0; i < 2; i++) {
        int row = srow + i * 32;
        cp16(sb + SM_K + SWZ(row * 128 + sc8 * 16),
             g_kh + (boff + row) * DDIM + sc8 * 8);
    }
    #pragma unroll
    for (int i = 0; i < 4; i++) {
        int k = hk + i * 16;
        cp16(sb + SM_H + hpanel * 8192 + SWZ(k * 128 + hpc8 * 16),
             g_hh + (boff + k) * CDIM + chbase + hc * 8);
    }
    CP_COMMIT();
    #pragma unroll
    for (int i = 0; i < 2; i++) {
        int row = srow + i * 32;
        cp16(sb + SM_K + 8192 + SWZ(row * 128 + sc8 * 16),
             g_kh + (boff + 64 + row) * DDIM + sc8 * 8);
    }
    #pragma unroll
    for (int i = 0; i < 4; i++) {
        int k = hk + i * 16;
        cp16(sb + SM_H + 16384 + hpanel * 8192 + SWZ(k * 128 + hpc8 * 16),
             g_hh + (boff + 64 + k) * CDIM + chbase + hc * 8);
    }
    CP_COMMIT();

    for (int t = 0; t < 64; t++) {
        if (t < 63) { CP_WAIT1(); } else { CP_WAIT0(); }
        __syncthreads();   // publish tile t; WAR: stage (t+2)%3 free

        if (t < 62) {
            const int kt2 = (t + 2) * 64;
            const int s2 = (t + 2) % 3;
            const uint32_t kbuf = sb + SM_K + s2 * 8192;
            const uint32_t hbuf = sb + SM_H + s2 * 16384;
            #pragma unroll
            for (int i = 0; i < 2; i++) {
                int row = srow + i * 32;
                cp16(kbuf + SWZ(row * 128 + sc8 * 16),
                     g_kh + (boff + kt2 + row) * DDIM + sc8 * 8);
            }
            #pragma unroll
            for (int i = 0; i < 4; i++) {
                int k = hk + i * 16;
                cp16(hbuf + hpanel * 8192 + SWZ(k * 128 + hpc8 * 16),
                     g_hh + (boff + kt2 + k) * CDIM + chbase + hc * 8);
            }
            CP_COMMIT();
        }

        if (t == 0) {
            #pragma unroll
            for (int ks = 0; ks < 4; ks++)
                ldsm4(qf[ks], sb + SM_Q + SWZ((q0 + l16) * 128 + ks * 32 + lhi));
        }

        const int st = t % 3;
        const uint32_t kb = sb + SM_K + st * 8192;
        const uint32_t hb = sb + SM_H + st * 16384;

        #pragma unroll
        for (int h = 0; h < 2; h++) {
            // ---- S = Q @ K^T (16q x 32k), fp16 accum ----
            uint32_t sacc[8] = {0, 0, 0, 0, 0, 0, 0, 0};
            #pragma unroll
            for (int ks = 0; ks < 4; ks++) {
                uint32_t b0[4], b1[4];
                ldsm4(b0, kb + SWZ((h * 32 + l16) * 128 + ks * 32 + lhi));
                ldsm4(b1, kb + SWZ((h * 32 + 16 + l16) * 128 + ks * 32 + lhi));
                mma16816f16(&sacc[0], qf[ks], b0[0], b0[2]);
                mma16816f16(&sacc[2], qf[ks], b0[1], b0[3]);
                mma16816f16(&sacc[4], qf[ks], b1[0], b1[2]);
                mma16816f16(&sacc[6], qf[ks], b1[1], b1[3]);
            }

            // ---- P = 2^S in place ----
            #pragma unroll
            for (int j = 0; j < 8; j++) sacc[j] = ex2h2(sacc[j]);

            // ---- denominators: dacc += P @ ones (fp32) ----
            mma16816(dacc, &sacc[0], ONES_H2, ONES_H2);
            mma16816(dacc, &sacc[4], ONES_H2, ONES_H2);

            // ---- PV: O += P @ H (16q x 128c), fp16 accum ----
            #pragma unroll
            for (int kpl = 0; kpl < 2; kpl++) {
                const int kk = h * 32 + kpl * 16;
                const uint32_t* a = &sacc[kpl * 4];
                #pragma unroll
                for (int cb = 0; cb < 8; cb++) {
                    const int panel = cb >> 2;
                    const int colb = (cb & 3) * 32;
                    uint32_t r[4];
                    ldsm4t(r, hb + panel * 8192 + SWZ((kk + l16) * 128 + colb + lhi));
                    mma16816f16(acc16[2 * cb],     a, r[0], r[1]);
                    mma16816f16(acc16[2 * cb + 1], a, r[2], r[3]);
                }
            }
        }
    }

    // ---- epilogue: out = gamma * o / denom + x (denoms warp-local) ----
    const float gv = gamma[0];
    const int r0 = q0 + (lane >> 2);
    const float s0 = gv / dacc[0];
    const float s1 = gv / dacc[2];
    #pragma unroll
    for (int j = 0; j < 16; j++) {
        const int cb = j >> 1, s = j & 1;
        const int c = chbase + cb * 16 + s * 8 + (lane & 3) * 2;
        size_t g0 = (boff + qbase + r0) * CDIM + c;
        size_t g1 = g0 + (size_t)8 * CDIM;
        float2 xv0 = *(const float2*)(x + g0);
        float2 xv1 = *(const float2*)(x + g1);
        float2 v0 = __half22float2(*(__half2*)&acc16[j][0]);
        float2 v1 = __half22float2(*(__half2*)&acc16[j][1]);
        float2 o0, o1;
        o0.x = s0 * v0.x + xv0.x;
        o0.y = s0 * v0.y + xv0.y;
        o1.x = s1 * v1.x + xv1.x;
        o1.y = s1 * v1.y + xv1.y;
        *(float2*)(out + g0) = o0;
        *(float2*)(out + g1) = o1;
    }
}

// ---------------------------------------------------------------------------
extern "C" void kernel_launch(void* const* d_in, const int* in_sizes, int n_in,
                              void* d_out, int out_size)
{
    const float* x     = (const float*)d_in[0];
    const float* in_h  = (const float*)d_in[1];
    const float* f     = (const float*)d_in[2];
    const float* g     = (const float*)d_in[3];
    const float* gamma = (const float*)d_in[4];
    float* out = (float*)d_out;

    cudaFuncSetAttribute(attn_kernel, cudaFuncAttributeMaxDynamicSharedMemorySize, SMEM_TOTAL);

    proj_kernel<<<dim3((NB * NSEQ) / 128, 1, 2), 256>>>(x, in_h, f, g);
    attn_kernel<<<dim3(NSEQ / 128, 4, NB), 256, SMEM_TOTAL>>>(x, gamma, out);
}

// round 11
// speedup vs baseline: 1.6306x; 1.1037x over previous
#include <cuda_runtime.h>
#include <cuda_fp16.h>
#include <cstdint>

#define NB   4
#define NSEQ 4096
#define CDIM 512
#define DDIM 64

// fp16 scratch (allocation-free rule: __device__ globals)
__device__ __half g_qh[NB * NSEQ * DDIM];   // Q = (x @ g) * log2e
__device__ __half g_kh[NB * NSEQ * DDIM];   // K = input_h @ f
__device__ __half g_hh[NB * NSEQ * CDIM];   // input_h fp16

#define SWZ(x) ((x) ^ (((x) >> 3) & 0x70))
#define ONES_H2 0x3C003C00u

// ---------------------------------------------------------------------------
__device__ __forceinline__ uint32_t smem_u32(const void* p) {
    uint32_t a;
    asm("{ .reg .u64 t; cvta.to.shared.u64 t, %1; cvt.u32.u64 %0, t; }" : "=r"(a) : "l"(p));
    return a;
}
__device__ __forceinline__ void cp16(uint32_t s, const void* g) {
    asm volatile("cp.async.cg.shared.global [%0], [%1], 16;" :: "r"(s), "l"(g));
}
#define CP_COMMIT() asm volatile("cp.async.commit_group;" ::: "memory")
#define CP_WAIT0()  asm volatile("cp.async.wait_group 0;" ::: "memory")

__device__ __forceinline__ void ldsm4(uint32_t* r, uint32_t a) {
    asm volatile("ldmatrix.sync.aligned.m8n8.x4.shared.b16 {%0,%1,%2,%3}, [%4];"
        : "=r"(r[0]), "=r"(r[1]), "=r"(r[2]), "=r"(r[3]) : "r"(a));
}
__device__ __forceinline__ void ldsm4t(uint32_t* r, uint32_t a) {
    asm volatile("ldmatrix.sync.aligned.m8n8.x4.trans.shared.b16 {%0,%1,%2,%3}, [%4];"
        : "=r"(r[0]), "=r"(r[1]), "=r"(r[2]), "=r"(r[3]) : "r"(a));
}
// fp32-accum HMMA
__device__ __forceinline__ void mma16816(float* d, const uint32_t* a,
                                         uint32_t b0, uint32_t b1) {
    asm volatile(
        "mma.sync.aligned.m16n8k16.row.col.f32.f16.f16.f32 "
        "{%0,%1,%2,%3}, {%4,%5,%6,%7}, {%8,%9}, {%0,%1,%2,%3};"
        : "+f"(d[0]), "+f"(d[1]), "+f"(d[2]), "+f"(d[3])
        : "r"(a[0]), "r"(a[1]), "r"(a[2]), "r"(a[3]), "r"(b0), "r"(b1));
}
// fp16-accum HMMA
__device__ __forceinline__ void mma16816f16(uint32_t* d, const uint32_t* a,
                                            uint32_t b0, uint32_t b1) {
    asm volatile(
        "mma.sync.aligned.m16n8k16.row.col.f16.f16.f16.f16 "
        "{%0,%1}, {%2,%3,%4,%5}, {%6,%7}, {%0,%1};"
        : "+r"(d[0]), "+r"(d[1])
        : "r"(a[0]), "r"(a[1]), "r"(a[2]), "r"(a[3]), "r"(b0), "r"(b1));
}
__device__ __forceinline__ uint32_t ex2h2(uint32_t v) {
    uint32_t r; asm("ex2.approx.f16x2 %0, %1;" : "=r"(r) : "r"(v)); return r;
}
__device__ __forceinline__ void sts128(uint32_t a, uint32_t v0, uint32_t v1,
                                       uint32_t v2, uint32_t v3) {
    asm volatile("st.shared.v4.b32 [%0], {%1,%2,%3,%4};"
        :: "r"(a), "r"(v0), "r"(v1), "r"(v2), "r"(v3) : "memory");
}

// ---------------------------------------------------------------------------
// Projection via HMMA: O[16384,64] = fp16(A[16384,512]) @ fp16(W[512,64]).
// Q output pre-scaled by log2e. doF writes g_hh too.
// ---------------------------------------------------------------------------
__global__ __launch_bounds__(256) void proj_kernel(
    const float* __restrict__ x, const float* __restrict__ in_h,
    const float* __restrict__ f, const float* __restrict__ g)
{
    const bool doF = (blockIdx.z == 1);
    const float* A  = doF ? in_h : x;
    const float* Wm = doF ? f : g;
    __half* O       = doF ? g_kh : g_qh;
    const float scaleO = doF ? 1.0f : 1.4426950408889634f;

    __shared__ char psm[16384 + 8192];
    const uint32_t sa = smem_u32(psm);
    const uint32_t sw = sa + 16384;

    const int m0  = blockIdx.x * 128;
    const int tid = threadIdx.x;
    const int wid = tid >> 5, lane = tid & 31;
    const int l16 = lane & 15, lhi = lane & 16;
    const int w16 = wid * 16;

    float acc[8][4];
    #pragma unroll
    for (int i = 0; i < 8; i++)
        #pragma unroll
        for (int j = 0; j < 4; j++) acc[i][j] = 0.f;

    for (int k0 = 0; k0 < CDIM; k0 += 64) {
        #pragma unroll
        for (int i = 0; i < 4; i++) {
            int lin = tid + i * 256;
            int row = lin >> 3, c8 = lin & 7;
            const float4* ap = (const float4*)(A + (size_t)(m0 + row) * CDIM + k0 + c8 * 8);
            float4 v0 = ap[0], v1 = ap[1];
            __half2 h0 = __floats2half2_rn(v0.x, v0.y);
            __half2 h1 = __floats2half2_rn(v0.z, v0.w);
            __half2 h2 = __floats2half2_rn(v1.x, v1.y);
            __half2 h3 = __floats2half2_rn(v1.z, v1.w);
            sts128(sa + SWZ(row * 128 + c8 * 16),
                   *(uint32_t*)&h0, *(uint32_t*)&h1, *(uint32_t*)&h2, *(uint32_t*)&h3);
            if (doF) {
                uint4 pk = make_uint4(*(uint32_t*)&h0, *(uint32_t*)&h1,
                                      *(uint32_t*)&h2, *(uint32_t*)&h3);
                *(uint4*)(g_hh + (size_t)(m0 + row) * CDIM + k0 + c8 * 8) = pk;
            }
        }
        #pragma unroll
        for (int i = 0; i < 2; i++) {
            int lin = tid + i * 256;
            int kk = lin >> 3, n8 = lin & 7;
            const float4* wp = (const float4*)(Wm + (size_t)(k0 + kk) * DDIM + n8 * 8);
            float4 v0 = wp[0], v1 = wp[1];
            __half2 h0 = __floats2half2_rn(v0.x, v0.y);
            __half2 h1 = __floats2half2_rn(v0.z, v0.w);
            __half2 h2 = __floats2half2_rn(v1.x, v1.y);
            __half2 h3 = __floats2half2_rn(v1.z, v1.w);
            sts128(sw + SWZ(kk * 128 + n8 * 16),
                   *(uint32_t*)&h0, *(uint32_t*)&h1, *(uint32_t*)&h2, *(uint32_t*)&h3);
        }
        __syncthreads();

        #pragma unroll
        for (int ks = 0; ks < 4; ks++) {
            uint32_t a[4];
            ldsm4(a, sa + SWZ((w16 + l16) * 128 + ks * 32 + lhi));
            #pragma unroll
            for (int cb = 0; cb < 4; cb++) {
                uint32_t b[4];
                ldsm4t(b, sw + SWZ((ks * 16 + l16) * 128 + cb * 32 + lhi));
                mma16816(acc[2 * cb],     a, b[0], b[1]);
                mma16816(acc[2 * cb + 1], a, b[2], b[3]);
            }
        }
        __syncthreads();
    }

    const int r = w16 + (lane >> 2);
    const int cb2 = (lane & 3) * 2;
    #pragma unroll
    for (int nt = 0; nt < 8; nt++) {
        __half2 v0 = __floats2half2_rn(scaleO * acc[nt][0], scaleO * acc[nt][1]);
        __half2 v1 = __floats2half2_rn(scaleO * acc[nt][2], scaleO * acc[nt][3]);
        *(__half2*)(O + (size_t)(m0 + r) * DDIM + nt * 8 + cb2)     = v0;
        *(__half2*)(O + (size_t)(m0 + r + 8) * DDIM + nt * 8 + cb2) = v1;
    }
}

// ---------------------------------------------------------------------------
// Fused attention: 256 thr / 8 warps; warp tile 16q x 256c; CTA 128q x 256c;
// KT=64; 2-stage cp.async, ONE barrier per iter; 2 CTAs/SM; fp16 PV accum;
// per-warp ones-MMA denominators. S duplication halved vs R10 (grid.y=2).
// SMEM: Q 16K | K 2x8K | H 2x32K = 98304 B
// ---------------------------------------------------------------------------
#define SM_Q     0
#define SM_K     16384
#define SM_H     32768
#define SMEM_TOTAL 98304

__global__ __launch_bounds__(256, 2)
void attn_kernel(const float* __restrict__ x, const float* __restrict__ gamma,
                 float* __restrict__ out)
{
    extern __shared__ char smem[];
    const uint32_t sb = smem_u32(smem);
    const int tid = threadIdx.x;
    const int wid = tid >> 5, lane = tid & 31;
    const int l16 = lane & 15;
    const int lhi = lane & 16;
    const int q0  = wid * 16;

    const int qt = blockIdx.x, ch = blockIdx.y, b = blockIdx.z;
    const int qbase = qt * 128, chbase = ch * 256;
    const size_t boff = (size_t)b * NSEQ;

    // fp16 accumulators: 32 n8-blocks x {rows r, rows r+8}
    uint32_t acc16[32][2];
    #pragma unroll
    for (int j = 0; j < 32; j++) { acc16[j][0] = 0u; acc16[j][1] = 0u; }
    float dacc[4] = {0.f, 0.f, 0.f, 0.f};
    uint32_t qf[4][4];

    // staging coords
    const int srow = tid >> 3, sc8 = tid & 7;   // Q/K: 32 rows per step
    const int hk = tid >> 5, hc = tid & 31;     // H: 8 rows per step, 32 c8 chunks
    const int hpanel = hc >> 3, hpc8 = hc & 7;

    // ---- Prologue: Q + tile 0 (one group) ----
    #pragma unroll
    for (int i = 0; i < 4; i++) {
        int row = srow + i * 32;
        cp16(sb + SM_Q + SWZ(row * 128 + sc8 * 16),
             g_qh + (boff + qbase + row) * DDIM + sc8 * 8);
    }
    #pragma unroll
    for (int i = 0; i < 2; i++) {
        int row = srow + i * 32;
        cp16(sb + SM_K + SWZ(row * 128 + sc8 * 16),
             g_kh + (boff + row) * DDIM + sc8 * 8);
    }
    #pragma unroll
    for (int i = 0; i < 8; i++) {
        int k = hk + i * 8;
        cp16(sb + SM_H + hpanel * 8192 + SWZ(k * 128 + hpc8 * 16),
             g_hh + (boff + k) * CDIM + chbase + hc * 8);
    }
    CP_COMMIT();

    for (int t = 0; t < 64; t++) {
        CP_WAIT0();        // tile t resident
        __syncthreads();   // publish t; all warps done with t-1 (frees buf (t+1)&1)

        if (t < 63) {
            const int kt1 = (t + 1) * 64;
            const int s1 = (t + 1) & 1;
            const uint32_t kbuf = sb + SM_K + s1 * 8192;
            const uint32_t hbuf = sb + SM_H + s1 * 32768;
            #pragma unroll
            for (int i = 0; i < 2; i++) {
                int row = srow + i * 32;
                cp16(kbuf + SWZ(row * 128 + sc8 * 16),
                     g_kh + (boff + kt1 + row) * DDIM + sc8 * 8);
            }
            #pragma unroll
            for (int i = 0; i < 8; i++) {
                int k = hk + i * 8;
                cp16(hbuf + hpanel * 8192 + SWZ(k * 128 + hpc8 * 16),
                     g_hh + (boff + kt1 + k) * CDIM + chbase + hc * 8);
            }
            CP_COMMIT();
        }

        if (t == 0) {
            #pragma unroll
            for (int ks = 0; ks < 4; ks++)
                ldsm4(qf[ks], sb + SM_Q + SWZ((q0 + l16) * 128 + ks * 32 + lhi));
        }

        const int st = t & 1;
        const uint32_t kb = sb + SM_K + st * 8192;
        const uint32_t hb = sb + SM_H + st * 32768;

        #pragma unroll
        for (int h = 0; h < 2; h++) {
            // ---- S = Q @ K^T (16q x 32k), fp16 accum ----
            uint32_t sacc[8] = {0, 0, 0, 0, 0, 0, 0, 0};
            #pragma unroll
            for (int ks = 0; ks < 4; ks++) {
                uint32_t b0[4], b1[4];
                ldsm4(b0, kb + SWZ((h * 32 + l16) * 128 + ks * 32 + lhi));
                ldsm4(b1, kb + SWZ((h * 32 + 16 + l16) * 128 + ks * 32 + lhi));
                mma16816f16(&sacc[0], qf[ks], b0[0], b0[2]);
                mma16816f16(&sacc[2], qf[ks], b0[1], b0[3]);
                mma16816f16(&sacc[4], qf[ks], b1[0], b1[2]);
                mma16816f16(&sacc[6], qf[ks], b1[1], b1[3]);
            }

            // ---- P = 2^S in place ----
            #pragma unroll
            for (int j = 0; j < 8; j++) sacc[j] = ex2h2(sacc[j]);

            // ---- denominators: dacc += P @ ones (fp32) ----
            mma16816(dacc, &sacc[0], ONES_H2, ONES_H2);
            mma16816(dacc, &sacc[4], ONES_H2, ONES_H2);

            // ---- PV: O += P @ H (16q x 256c), fp16 accum ----
            #pragma unroll
            for (int kpl = 0; kpl < 2; kpl++) {
                const int kk = h * 32 + kpl * 16;
                const uint32_t* a = &sacc[kpl * 4];
                #pragma unroll
                for (int cb = 0; cb < 16; cb++) {
                    const int panel = cb >> 2;
                    const int colb = (cb & 3) * 32;
                    uint32_t r[4];
                    ldsm4t(r, hb + panel * 8192 + SWZ((kk + l16) * 128 + colb + lhi));
                    mma16816f16(acc16[2 * cb],     a, r[0], r[1]);
                    mma16816f16(acc16[2 * cb + 1], a, r[2], r[3]);
                }
            }
        }
    }

    // ---- epilogue: out = gamma * o / denom + x (denoms warp-local) ----
    const float gv = gamma[0];
    const int r0 = q0 + (lane >> 2);
    const float s0 = gv / dacc[0];
    const float s1 = gv / dacc[2];
    #pragma unroll
    for (int j = 0; j < 32; j++) {
        const int cb = j >> 1, s = j & 1;
        const int c = chbase + cb * 16 + s * 8 + (lane & 3) * 2;
        size_t g0 = (boff + qbase + r0) * CDIM + c;
        size_t g1 = g0 + (size_t)8 * CDIM;
        float2 xv0 = *(const float2*)(x + g0);
        float2 xv1 = *(const float2*)(x + g1);
        float2 v0 = __half22float2(*(__half2*)&acc16[j][0]);
        float2 v1 = __half22float2(*(__half2*)&acc16[j][1]);
        float2 o0, o1;
        o0.x = s0 * v0.x + xv0.x;
        o0.y = s0 * v0.y + xv0.y;
        o1.x = s1 * v1.x + xv1.x;
        o1.y = s1 * v1.y + xv1.y;
        *(float2*)(out + g0) = o0;
        *(float2*)(out + g1) = o1;
    }
}

// ---------------------------------------------------------------------------
extern "C" void kernel_launch(void* const* d_in, const int* in_sizes, int n_in,
                              void* d_out, int out_size)
{
    const float* x     = (const float*)d_in[0];
    const float* in_h  = (const float*)d_in[1];
    const float* f     = (const float*)d_in[2];
    const float* g     = (const float*)d_in[3];
    const float* gamma = (const float*)d_in[4];
    float* out = (float*)d_out;

    cudaFuncSetAttribute(attn_kernel, cudaFuncAttributeMaxDynamicSharedMemorySize, SMEM_TOTAL);

    proj_kernel<<<dim3((NB * NSEQ) / 128, 1, 2), 256>>>(x, in_h, f, g);
    attn_kernel<<<dim3(NSEQ / 128, 2, NB), 256, SMEM_TOTAL>>>(x, gamma, out);
}